// round 1
// baseline (speedup 1.0000x reference)
#include <cuda_runtime.h>
#include <math.h>

#define B   64
#define H   1024
#define G4  4096
#define LEN 128
#define KC  32          // K chunk staged in smem
#define HT  8           // hidden units per block
#define NCOLS 32        // 4 gates * HT
#define NTHREADS 128

// Persistent state (no allocations allowed): h is parity ping-ponged per layer,
// c is updated in place (each block owns its hidden slice exclusively).
__device__ float g_h[2][2][B * H];   // [layer][parity][b*H+n]
__device__ float g_c[2][B * H];      // [layer][b*H+n]

__global__ void init_state(const float* __restrict__ h0, const float* __restrict__ c0) {
    int i = blockIdx.x * blockDim.x + threadIdx.x;
    int n = 2 * B * H;
    if (i < n) {
        int l = i / (B * H), r = i % (B * H);
        g_h[l][0][r] = h0[i];
        g_c[l][r]    = c0[i];
    }
}

__device__ __forceinline__ unsigned long long fma2(unsigned long long a,
                                                   unsigned long long b,
                                                   unsigned long long c) {
    unsigned long long d;
    asm("fma.rn.f32x2 %0, %1, %2, %3;" : "=l"(d) : "l"(a), "l"(b), "l"(c));
    return d;
}
__device__ __forceinline__ unsigned long long pack2(float w) {
    unsigned long long r;
    asm("mov.b64 %0, {%1, %1};" : "=l"(r) : "f"(w));
    return r;
}
__device__ __forceinline__ float2 unpack2(unsigned long long v) {
    float2 r;
    asm("mov.b64 {%0, %1}, %2;" : "=f"(r.x), "=f"(r.y) : "l"(v));
    return r;
}

// One (timestep, layer) update, fully fused: gates GEMM + bias + activations +
// state update + (layer 1) output write.
// Block: 8 hidden units, all 4 gates, all 64 batches -> 32 W-rows x 64 batches.
__global__ __launch_bounds__(NTHREADS, 1) void lstm_step(
    const float* __restrict__ xext,   // external input, used iff layer==0 && t==0
    const float* __restrict__ Wih,    // this layer's [4096][1024]
    const float* __restrict__ Whh,    // this layer's [4096][1024]
    const float* __restrict__ bih,    // this layer's [4096]
    const float* __restrict__ bhh,    // this layer's [4096]
    float* __restrict__ out,          // nullptr for layer 0; else [B][LEN][H]
    int layer, int t)
{
    __shared__ __align__(16) float A[KC][B + 2];        // activations, [k][batch], stride 66
    __shared__ float Wsm[NCOLS][KC + 1];                // weights, [col][k]
    __shared__ float gsm[NCOLS][B];                     // gate results

    const int tid  = threadIdx.x;
    const int hid0 = blockIdx.x * HT;

    const float* xin;
    if (layer == 0) xin = (t == 0) ? xext : g_h[1][t & 1];
    else            xin = g_h[0][(t + 1) & 1];          // layer 0 just wrote this parity
    const float* hin  = g_h[layer][t & 1];
    float*       hout = g_h[layer][(t + 1) & 1];
    float*       cbuf = g_c[layer];

    // thread tile: tx -> batch octet (8 batches), ty -> 2 gate-columns
    const int tx = tid & 7;
    const int ty = tid >> 3;        // 0..15
    const int c0 = ty * 2;

    unsigned long long acc[4][2];
#pragma unroll
    for (int p = 0; p < 4; ++p)
#pragma unroll
        for (int j = 0; j < 2; ++j) acc[p][j] = 0ull;

    for (int seg = 0; seg < 2; ++seg) {
        const float* act = seg ? hin : xin;
        const float* Wp  = seg ? Whh : Wih;
        for (int k0 = 0; k0 < H; k0 += KC) {
            __syncthreads();
            // Stage A chunk: 64 batches x 32 k, transposed to [k][batch]
            {
                int bb = tid >> 1, half = tid & 1;
                const float4* src = (const float4*)(act + bb * H + k0 + half * 16);
#pragma unroll
                for (int q = 0; q < 4; ++q) {
                    float4 v = src[q];
                    int kk = half * 16 + q * 4;
                    A[kk + 0][bb] = v.x; A[kk + 1][bb] = v.y;
                    A[kk + 2][bb] = v.z; A[kk + 3][bb] = v.w;
                }
            }
            // Stage W chunk: 32 rows (4 gates x 8 hidden) x 32 k
            {
                int col = tid >> 2, kq = tid & 3;
                int g = col >> 3, hh = col & 7;
                const float* wrow = Wp + (size_t)(g * H + hid0 + hh) * H + k0 + kq * 8;
                float4 v0 = ((const float4*)wrow)[0];
                float4 v1 = ((const float4*)wrow)[1];
                int kb = kq * 8;
                Wsm[col][kb + 0] = v0.x; Wsm[col][kb + 1] = v0.y;
                Wsm[col][kb + 2] = v0.z; Wsm[col][kb + 3] = v0.w;
                Wsm[col][kb + 4] = v1.x; Wsm[col][kb + 5] = v1.y;
                Wsm[col][kb + 6] = v1.z; Wsm[col][kb + 7] = v1.w;
            }
            __syncthreads();
#pragma unroll
            for (int kk = 0; kk < KC; ++kk) {
                const unsigned long long* arow =
                    (const unsigned long long*)&A[kk][tx * 8];
                unsigned long long a0 = arow[0], a1 = arow[1];
                unsigned long long a2 = arow[2], a3 = arow[3];
                unsigned long long w0 = pack2(Wsm[c0][kk]);
                unsigned long long w1 = pack2(Wsm[c0 + 1][kk]);
                acc[0][0] = fma2(a0, w0, acc[0][0]); acc[0][1] = fma2(a0, w1, acc[0][1]);
                acc[1][0] = fma2(a1, w0, acc[1][0]); acc[1][1] = fma2(a1, w1, acc[1][1]);
                acc[2][0] = fma2(a2, w0, acc[2][0]); acc[2][1] = fma2(a2, w1, acc[2][1]);
                acc[3][0] = fma2(a3, w0, acc[3][0]); acc[3][1] = fma2(a3, w1, acc[3][1]);
            }
        }
    }

    // Dump accumulators to smem for the cross-gate pointwise stage
#pragma unroll
    for (int p = 0; p < 4; ++p)
#pragma unroll
        for (int j = 0; j < 2; ++j) {
            float2 v = unpack2(acc[p][j]);
            gsm[c0 + j][tx * 8 + 2 * p]     = v.x;
            gsm[c0 + j][tx * 8 + 2 * p + 1] = v.y;
        }
    __syncthreads();

    // Pointwise LSTM cell update for this block's 8 hidden x 64 batches
    for (int e = tid; e < HT * B; e += NTHREADS) {
        int bb = e >> 3, hh = e & 7;
        int n = hid0 + hh;
        float iv = gsm[hh][bb]      + bih[n]         + bhh[n];
        float fv = gsm[8 + hh][bb]  + bih[H + n]     + bhh[H + n];
        float gv = gsm[16 + hh][bb] + bih[2 * H + n] + bhh[2 * H + n];
        float ov = gsm[24 + hh][bb] + bih[3 * H + n] + bhh[3 * H + n];
        float si = 1.0f / (1.0f + expf(-iv));
        float sf = 1.0f / (1.0f + expf(-fv));
        float so = 1.0f / (1.0f + expf(-ov));
        float tg = tanhf(gv);
        float cp = cbuf[bb * H + n];
        float cn = sf * cp + si * tg;
        float hn = so * tanhf(cn);
        cbuf[bb * H + n] = cn;
        hout[bb * H + n] = hn;
        if (out) out[((size_t)bb * LEN + t) * H + n] = hn;
    }
}

extern "C" void kernel_launch(void* const* d_in, const int* in_sizes, int n_in,
                              void* d_out, int out_size) {
    const float* x0  = (const float*)d_in[0];   // [64,1,1024]
    const float* h0  = (const float*)d_in[1];   // [2,64,1024]
    const float* c0  = (const float*)d_in[2];   // [2,64,1024]
    const float* Wih = (const float*)d_in[3];   // [2,4096,1024]
    const float* Whh = (const float*)d_in[4];   // [2,4096,1024]
    const float* bih = (const float*)d_in[5];   // [2,4096]
    const float* bhh = (const float*)d_in[6];   // [2,4096]
    float* out = (float*)d_out;                 // [64,128,1024]

    init_state<<<(2 * B * H + 255) / 256, 256>>>(h0, c0);

    for (int t = 0; t < LEN; ++t) {
        lstm_step<<<H / HT, NTHREADS>>>(x0, Wih, Whh, bih, bhh,
                                        nullptr, 0, t);
        lstm_step<<<H / HT, NTHREADS>>>(nullptr,
                                        Wih + (size_t)G4 * H, Whh + (size_t)G4 * H,
                                        bih + G4, bhh + G4,
                                        out, 1, t);
    }
}

// round 4
// speedup vs baseline: 1.0043x; 1.0043x over previous
#include <cuda_runtime.h>
#include <math.h>

#define B   64
#define H   1024
#define G4  4096
#define LEN 128
#define KC  32          // K chunk staged in smem
#define HT  8           // hidden units per block
#define NCOLS 32        // 4 gates * HT
#define NTHREADS 128

// Persistent state (no allocations allowed): h is parity ping-ponged per layer,
// c is updated in place (each block owns its hidden slice exclusively).
__device__ float g_h[2][2][B * H];   // [layer][parity][b*H+n]
__device__ float g_c[2][B * H];      // [layer][b*H+n]

__global__ void init_state(const float* __restrict__ h0, const float* __restrict__ c0) {
    int i = blockIdx.x * blockDim.x + threadIdx.x;
    int n = 2 * B * H;
    if (i < n) {
        int l = i / (B * H), r = i % (B * H);
        g_h[l][0][r] = h0[i];
        g_c[l][r]    = c0[i];
    }
}

__device__ __forceinline__ unsigned long long fma2(unsigned long long a,
                                                   unsigned long long b,
                                                   unsigned long long c) {
    unsigned long long d;
    asm("fma.rn.f32x2 %0, %1, %2, %3;" : "=l"(d) : "l"(a), "l"(b), "l"(c));
    return d;
}
__device__ __forceinline__ unsigned long long pack2(float w) {
    unsigned long long r;
    asm("mov.b64 %0, {%1, %1};" : "=l"(r) : "f"(w));
    return r;
}
__device__ __forceinline__ float2 unpack2(unsigned long long v) {
    float2 r;
    asm("mov.b64 {%0, %1}, %2;" : "=f"(r.x), "=f"(r.y) : "l"(v));
    return r;
}

// One (timestep, layer) update, fully fused: gates GEMM + bias + activations +
// state update + (layer 1) output write.
// Block: 8 hidden units, all 4 gates, all 64 batches -> 32 W-rows x 64 batches.
__global__ __launch_bounds__(NTHREADS, 1) void lstm_step(
    const float* __restrict__ xext,   // external input, used iff layer==0 && t==0
    const float* __restrict__ Wih,    // this layer's [4096][1024]
    const float* __restrict__ Whh,    // this layer's [4096][1024]
    const float* __restrict__ bih,    // this layer's [4096]
    const float* __restrict__ bhh,    // this layer's [4096]
    float* __restrict__ out,          // nullptr for layer 0; else [B][LEN][H]
    int layer, int t)
{
    __shared__ __align__(16) float A[KC][B + 2];        // activations, [k][batch], stride 66
    __shared__ float Wsm[NCOLS][KC + 1];                // weights, [col][k]
    __shared__ float gsm[NCOLS][B];                     // gate results

    const int tid  = threadIdx.x;
    const int hid0 = blockIdx.x * HT;

    const float* xin;
    if (layer == 0) xin = (t == 0) ? xext : g_h[1][t & 1];
    else            xin = g_h[0][(t + 1) & 1];          // layer 0 just wrote this parity
    const float* hin  = g_h[layer][t & 1];
    float*       hout = g_h[layer][(t + 1) & 1];
    float*       cbuf = g_c[layer];

    // thread tile: tx -> batch octet (8 batches), ty -> 2 gate-columns
    const int tx = tid & 7;
    const int ty = tid >> 3;        // 0..15
    const int c0 = ty * 2;

    unsigned long long acc[4][2];
#pragma unroll
    for (int p = 0; p < 4; ++p)
#pragma unroll
        for (int j = 0; j < 2; ++j) acc[p][j] = 0ull;

    for (int seg = 0; seg < 2; ++seg) {
        const float* act = seg ? hin : xin;
        const float* Wp  = seg ? Whh : Wih;
        for (int k0 = 0; k0 < H; k0 += KC) {
            __syncthreads();
            // Stage A chunk: 64 batches x 32 k, transposed to [k][batch]
            {
                int bb = tid >> 1, half = tid & 1;
                const float4* src = (const float4*)(act + bb * H + k0 + half * 16);
#pragma unroll
                for (int q = 0; q < 4; ++q) {
                    float4 v = src[q];
                    int kk = half * 16 + q * 4;
                    A[kk + 0][bb] = v.x; A[kk + 1][bb] = v.y;
                    A[kk + 2][bb] = v.z; A[kk + 3][bb] = v.w;
                }
            }
            // Stage W chunk: 32 rows (4 gates x 8 hidden) x 32 k
            {
                int col = tid >> 2, kq = tid & 3;
                int g = col >> 3, hh = col & 7;
                const float* wrow = Wp + (size_t)(g * H + hid0 + hh) * H + k0 + kq * 8;
                float4 v0 = ((const float4*)wrow)[0];
                float4 v1 = ((const float4*)wrow)[1];
                int kb = kq * 8;
                Wsm[col][kb + 0] = v0.x; Wsm[col][kb + 1] = v0.y;
                Wsm[col][kb + 2] = v0.z; Wsm[col][kb + 3] = v0.w;
                Wsm[col][kb + 4] = v1.x; Wsm[col][kb + 5] = v1.y;
                Wsm[col][kb + 6] = v1.z; Wsm[col][kb + 7] = v1.w;
            }
            __syncthreads();
#pragma unroll
            for (int kk = 0; kk < KC; ++kk) {
                const unsigned long long* arow =
                    (const unsigned long long*)&A[kk][tx * 8];
                unsigned long long a0 = arow[0], a1 = arow[1];
                unsigned long long a2 = arow[2], a3 = arow[3];
                unsigned long long w0 = pack2(Wsm[c0][kk]);
                unsigned long long w1 = pack2(Wsm[c0 + 1][kk]);
                acc[0][0] = fma2(a0, w0, acc[0][0]); acc[0][1] = fma2(a0, w1, acc[0][1]);
                acc[1][0] = fma2(a1, w0, acc[1][0]); acc[1][1] = fma2(a1, w1, acc[1][1]);
                acc[2][0] = fma2(a2, w0, acc[2][0]); acc[2][1] = fma2(a2, w1, acc[2][1]);
                acc[3][0] = fma2(a3, w0, acc[3][0]); acc[3][1] = fma2(a3, w1, acc[3][1]);
            }
        }
    }

    // Dump accumulators to smem for the cross-gate pointwise stage
#pragma unroll
    for (int p = 0; p < 4; ++p)
#pragma unroll
        for (int j = 0; j < 2; ++j) {
            float2 v = unpack2(acc[p][j]);
            gsm[c0 + j][tx * 8 + 2 * p]     = v.x;
            gsm[c0 + j][tx * 8 + 2 * p + 1] = v.y;
        }
    __syncthreads();

    // Pointwise LSTM cell update for this block's 8 hidden x 64 batches
    for (int e = tid; e < HT * B; e += NTHREADS) {
        int bb = e >> 3, hh = e & 7;
        int n = hid0 + hh;
        float iv = gsm[hh][bb]      + bih[n]         + bhh[n];
        float fv = gsm[8 + hh][bb]  + bih[H + n]     + bhh[H + n];
        float gv = gsm[16 + hh][bb] + bih[2 * H + n] + bhh[2 * H + n];
        float ov = gsm[24 + hh][bb] + bih[3 * H + n] + bhh[3 * H + n];
        float si = 1.0f / (1.0f + expf(-iv));
        float sf = 1.0f / (1.0f + expf(-fv));
        float so = 1.0f / (1.0f + expf(-ov));
        float tg = tanhf(gv);
        float cp = cbuf[bb * H + n];
        float cn = sf * cp + si * tg;
        float hn = so * tanhf(cn);
        cbuf[bb * H + n] = cn;
        hout[bb * H + n] = hn;
        if (out) out[((size_t)bb * LEN + t) * H + n] = hn;
    }
}

extern "C" void kernel_launch(void* const* d_in, const int* in_sizes, int n_in,
                              void* d_out, int out_size) {
    const float* x0  = (const float*)d_in[0];   // [64,1,1024]
    const float* h0  = (const float*)d_in[1];   // [2,64,1024]
    const float* c0  = (const float*)d_in[2];   // [2,64,1024]
    const float* Wih = (const float*)d_in[3];   // [2,4096,1024]
    const float* Whh = (const float*)d_in[4];   // [2,4096,1024]
    const float* bih = (const float*)d_in[5];   // [2,4096]
    const float* bhh = (const float*)d_in[6];   // [2,4096]
    float* out = (float*)d_out;                 // [64,128,1024]

    init_state<<<(2 * B * H + 255) / 256, 256>>>(h0, c0);

    for (int t = 0; t < LEN; ++t) {
        lstm_step<<<H / HT, NTHREADS>>>(x0, Wih, Whh, bih, bhh,
                                        nullptr, 0, t);
        lstm_step<<<H / HT, NTHREADS>>>(nullptr,
                                        Wih + (size_t)G4 * H, Whh + (size_t)G4 * H,
                                        bih + G4, bhh + G4,
                                        out, 1, t);
    }
}

// round 6
// speedup vs baseline: 6.3716x; 6.3446x over previous
#include <cuda_runtime.h>
#include <cuda_bf16.h>
#include <stdint.h>
#include <math.h>

#define BATCH 64
#define HID   1024
#define LEN   128

#define WSTG   8192            // W stage: 32 rows x 64 k, hi(4KB) + lo(4KB)
#define VSTG   16384           // V stage: 64 rows x 64 k, hi(8KB) + lo(8KB)
#define NSTAGES 32             // K=2048 in 64-chunks (stages 0-15: seg ih, 16-31: seg hh)
#define CTA_WB ((size_t)NSTAGES * WSTG)     // 256KB per (layer, cta)
#define STGB   (WSTG + VSTG)   // 24576 bytes per smem stage

#define SMEM_ST0 1024
#define SMEM_GSM (SMEM_ST0 + 2 * STGB)      // 50176
#define GSM_STRIDE 68
#define SMEM_TOTAL (SMEM_GSM + 32 * GSM_STRIDE * 4)   // 58880

#define SWZ(x) ((x) ^ (((x) >> 3) & 0x70))

// ----------------- persistent device state (no runtime allocations) ---------
__device__ __align__(1024) char Wpack[2u * 128u * 262144u];   // 64MB
__device__ __align__(1024) char Vx[16 * VSTG];
__device__ __align__(1024) char V0[2][16 * VSTG];
__device__ __align__(1024) char V1[2][16 * VSTG];
__device__ float Cst[2][BATCH * HID];
__device__ float Bpack[2][4096];

// ----------------- PTX helpers ----------------------------------------------
__device__ __forceinline__ uint32_t smem_u32(const void* p) {
    uint32_t a;
    asm("{ .reg .u64 t; cvta.to.shared.u64 t, %1; cvt.u32.u64 %0, t; }" : "=r"(a) : "l"(p));
    return a;
}
#define MBAR_INIT(a, c) asm volatile("mbarrier.init.shared.b64 [%0], %1;" :: "r"(a), "r"(c) : "memory")
#define MBAR_EXPECT_TX(a, tx) asm volatile("mbarrier.arrive.expect_tx.shared.b64 _, [%0], %1;" :: "r"(a), "r"(tx) : "memory")
#define MBAR_WAIT(addr, ph) do {                                              \
    uint32_t _m = (addr), _p = (ph), _d;                                      \
    asm volatile("{\n\t.reg .pred p;\n\t"                                     \
        "mbarrier.try_wait.parity.acquire.cta.shared::cta.b64 p, [%1], %2;\n\t" \
        "selp.b32 %0, 1, 0, p;\n\t}" : "=r"(_d) : "r"(_m), "r"(_p) : "memory"); \
    if (!_d) {                                                                \
        asm volatile("{\n\t.reg .pred P1;\n\t"                                \
            "WL%=:\n\t"                                                       \
            "mbarrier.try_wait.parity.acquire.cta.shared::cta.b64 P1, [%0], %1, 0x989680;\n\t" \
            "@P1 bra.uni WD%=;\n\t"                                           \
            "bra.uni WL%=;\n\t"                                               \
            "WD%=:\n\t}" :: "r"(_m), "r"(_p) : "memory");                     \
    } } while (0)

#define BULK_G2S(dst, src, bytes, mbar)                                       \
    asm volatile("cp.async.bulk.shared::cta.global.mbarrier::complete_tx::bytes [%0], [%1], %2, [%3];" \
        :: "r"(dst), "l"(src), "r"(bytes), "r"(mbar) : "memory")

__device__ __forceinline__ void ldmx4(uint32_t* r, uint32_t addr) {
    asm volatile("ldmatrix.sync.aligned.m8n8.x4.shared.b16 {%0,%1,%2,%3}, [%4];"
        : "=r"(r[0]), "=r"(r[1]), "=r"(r[2]), "=r"(r[3]) : "r"(addr));
}
__device__ __forceinline__ void mma16816(float* d, const uint32_t* a, const uint32_t* b) {
    asm volatile("mma.sync.aligned.m16n8k16.row.col.f32.bf16.bf16.f32 "
        "{%0,%1,%2,%3}, {%4,%5,%6,%7}, {%8,%9}, {%0,%1,%2,%3};"
        : "+f"(d[0]), "+f"(d[1]), "+f"(d[2]), "+f"(d[3])
        : "r"(a[0]), "r"(a[1]), "r"(a[2]), "r"(a[3]), "r"(b[0]), "r"(b[1]));
}
__device__ __forceinline__ void split_bf16(float v, __nv_bfloat16& hi, __nv_bfloat16& lo) {
    hi = __float2bfloat16(v);
    lo = __float2bfloat16(v - __bfloat162float(hi));
}
__device__ __forceinline__ float sigm(float x) { return 1.0f / (1.0f + __expf(-x)); }
__device__ __forceinline__ float tanh_f(float x) {
    float ax = fabsf(x);
    float t  = __expf(-2.0f * ax);
    return copysignf((1.0f - t) / (1.0f + t), x);
}

// ----------------- one-time (per replay) weight packing ----------------------
// CTA bid (0..127) owns hidden units u = bid*8 + j. Tile row tr = gate*8 + j
// (32 rows). Stage = seg*16 + k/64. Layout per (l,bid): stage*WSTG + SWZ(tr*128
// + kk*2), hi at +0, lo at +4096. seg0 = W_ih, seg1 = W_hh.
__global__ void convert_weights(const float* __restrict__ Wih,
                                const float* __restrict__ Whh) {
    unsigned gid = blockIdx.x * blockDim.x + threadIdx.x;   // < 2097152
    unsigned l    = gid >> 20;
    unsigned rest = gid & 0xFFFFF;
    unsigned seg  = rest >> 19;
    unsigned r2   = rest & 0x7FFFF;
    unsigned r    = r2 >> 7;            // weight row 0..4095
    unsigned k8   = r2 & 127;           // k block of 8

    const float* src = (seg ? Whh : Wih) + (size_t)l * 4096u * 1024u
                     + (size_t)r * 1024u + k8 * 8u;
    float4 v0 = ((const float4*)src)[0];
    float4 v1 = ((const float4*)src)[1];
    float vs[8] = {v0.x, v0.y, v0.z, v0.w, v1.x, v1.y, v1.z, v1.w};

    __nv_bfloat16 hi[8], lo[8];
#pragma unroll
    for (int e = 0; e < 8; e++) split_bf16(vs[e], hi[e], lo[e]);

    unsigned gate = r >> 10, u = r & 1023, bid = u >> 3, j = u & 7;
    unsigned tr = gate * 8 + j;
    unsigned k0 = k8 * 8, stg = seg * 16 + (k0 >> 6), kk = k0 & 63;
    unsigned off = SWZ(tr * 128 + kk * 2);                  // 16B aligned
    char* base = Wpack + ((size_t)(l * 128 + bid)) * CTA_WB + stg * WSTG;

    __nv_bfloat162 p0(hi[0], hi[1]), p1(hi[2], hi[3]), p2(hi[4], hi[5]), p3(hi[6], hi[7]);
    __nv_bfloat162 q0(lo[0], lo[1]), q1(lo[2], lo[3]), q2(lo[4], lo[5]), q3(lo[6], lo[7]);
    *(uint4*)(base + off) =
        make_uint4(*(uint32_t*)&p0, *(uint32_t*)&p1, *(uint32_t*)&p2, *(uint32_t*)&p3);
    *(uint4*)(base + off + 4096) =
        make_uint4(*(uint32_t*)&q0, *(uint32_t*)&q1, *(uint32_t*)&q2, *(uint32_t*)&q3);
}

// ----------------- init: c, biases, initial activation packs -----------------
__global__ void init_misc(const float* __restrict__ x0, const float* __restrict__ h0,
                          const float* __restrict__ c0, const float* __restrict__ bih,
                          const float* __restrict__ bhh) {
    unsigned i = blockIdx.x * blockDim.x + threadIdx.x;     // 131072 threads
    if (i < 131072) ((float*)Cst)[i] = c0[i];
    if (i < 8192) {
        unsigned l = i >> 12, R = i & 4095;
        unsigned bid = R >> 5, rr = R & 31, gate = rr >> 3, j = rr & 7;
        unsigned u = bid * 8 + j;
        unsigned s = l * 4096 + gate * 1024 + u;
        Bpack[l][R] = bih[s] + bhh[s];
    }
    if (i < 3 * 8192) {                                     // activation packing
        unsigned m = i >> 13;                               // 0=Vx, 1=V0, 2=V1
        unsigned p = i & 8191;
        unsigned b = p >> 7, k8 = p & 127, k0 = k8 * 8;
        const float* src = (m == 0) ? (x0 + b * 1024 + k0)
                         : (h0 + (m - 1) * 65536 + b * 1024 + k0);
        char* buf = (m == 0) ? Vx : (m == 1 ? V0[0] : V1[0]);
        float4 v0 = ((const float4*)src)[0];
        float4 v1 = ((const float4*)src)[1];
        float vs[8] = {v0.x, v0.y, v0.z, v0.w, v1.x, v1.y, v1.z, v1.w};
        __nv_bfloat16 hi[8], lo[8];
#pragma unroll
        for (int e = 0; e < 8; e++) split_bf16(vs[e], hi[e], lo[e]);
        unsigned stg = k0 >> 6, kk = k0 & 63;
        unsigned off = SWZ(b * 128 + kk * 2);
        __nv_bfloat162 p0(hi[0], hi[1]), p1(hi[2], hi[3]), p2(hi[4], hi[5]), p3(hi[6], hi[7]);
        __nv_bfloat162 q0(lo[0], lo[1]), q1(lo[2], lo[3]), q2(lo[4], lo[5]), q3(lo[6], lo[7]);
        *(uint4*)(buf + stg * VSTG + off) =
            make_uint4(*(uint32_t*)&p0, *(uint32_t*)&p1, *(uint32_t*)&p2, *(uint32_t*)&p3);
        *(uint4*)(buf + stg * VSTG + 8192 + off) =
            make_uint4(*(uint32_t*)&q0, *(uint32_t*)&q1, *(uint32_t*)&q2, *(uint32_t*)&q3);
    }
}

// ----------------- per (t, layer) fused step ---------------------------------
// CTA bid: units u = bid*8..+7, all gates, all 64 batches. M=32, N=64, K=2048.
// 4 warps, each M16 x N32.
__global__ void __launch_bounds__(128, 1)
lstm_step_mma(int l, int t, float* __restrict__ out) {
    extern __shared__ __align__(1024) char smem[];
    uint32_t sb = smem_u32(smem);
    const int tid = threadIdx.x, wid = tid >> 5, lid = tid & 31;
    const int bid = blockIdx.x;

    if (tid == 0) { MBAR_INIT(sb + 0, 1); MBAR_INIT(sb + 8, 1); }
    __syncthreads();

    const char* Wc = Wpack + (size_t)(l * 128 + bid) * CTA_WB;
    const char* Vs0 = (l == 0) ? ((t == 0) ? Vx : V1[t & 1]) : V0[(t + 1) & 1];
    const char* Vs1 = (l == 0) ? V0[t & 1] : V1[t & 1];
    char*       Vdst = (l == 0) ? V0[(t + 1) & 1] : V1[(t + 1) & 1];
    const float* Bp = Bpack[l];
    float*       Cp = Cst[l];

    // per-lane ldmatrix relative byte offsets
    const int mrow  = (wid >> 1) * 16;
    const int ncol0 = (wid & 1) * 32;
    const int blk = lid >> 3, rin = lid & 7;
    const unsigned rbA  = (unsigned)((mrow + (blk & 1) * 8 + rin) * 128 + (blk >> 1) * 16);
    const unsigned rbB0 = (unsigned)((ncol0 + (blk >> 1) * 8 + rin) * 128 + (blk & 1) * 16);
    const unsigned rbB1 = rbB0 + 16 * 128;

    float acc[4][4];
#pragma unroll
    for (int g = 0; g < 4; g++)
#pragma unroll
        for (int e = 0; e < 4; e++) acc[g][e] = 0.0f;

    // prologue: stage 0 load
    if (tid == 0) {
        MBAR_EXPECT_TX(sb + 0, STGB);
        BULK_G2S(sb + SMEM_ST0, Wc, WSTG, sb + 0);
        BULK_G2S(sb + SMEM_ST0 + WSTG, Vs0, VSTG, sb + 0);
    }

    for (int s = 0; s < NSTAGES; s++) {
        const int buf = s & 1;
        if (s + 1 < NSTAGES && tid == 0) {       // issue next stage into other buf
            const int nb = (s + 1) & 1;
            uint32_t fb = sb + nb * 8;
            MBAR_EXPECT_TX(fb, STGB);
            uint32_t sdst = sb + SMEM_ST0 + nb * STGB;
            const int ns = s + 1;
            const char* vsrc = ((ns < 16) ? Vs0 : Vs1) + (size_t)(ns & 15) * VSTG;
            BULK_G2S(sdst, Wc + (size_t)ns * WSTG, WSTG, fb);
            BULK_G2S(sdst + WSTG, vsrc, VSTG, fb);
        }
        MBAR_WAIT(sb + buf * 8, (s >> 1) & 1);

        const uint32_t wb = sb + SMEM_ST0 + buf * STGB;
        const uint32_t vb = wb + WSTG;
#pragma unroll
        for (int kc = 0; kc < 4; kc++) {
            uint32_t ahi[4], alo[4], bhi[8], blo[8];
            const unsigned ko = kc * 32;
            ldmx4(ahi, wb + SWZ(rbA + ko));
            ldmx4(alo, wb + 4096 + SWZ(rbA + ko));
            ldmx4(bhi,     vb + SWZ(rbB0 + ko));
            ldmx4(bhi + 4, vb + SWZ(rbB1 + ko));
            ldmx4(blo,     vb + 8192 + SWZ(rbB0 + ko));
            ldmx4(blo + 4, vb + 8192 + SWZ(rbB1 + ko));
#pragma unroll
            for (int g = 0; g < 4; g++) {
                const uint32_t* bh = bhi + (g >> 1) * 4 + (g & 1) * 2;
                const uint32_t* bl = blo + (g >> 1) * 4 + (g & 1) * 2;
                mma16816(acc[g], ahi, bh);
                mma16816(acc[g], ahi, bl);
                mma16816(acc[g], alo, bh);
            }
        }
        __syncthreads();                         // empty barrier for this buf
    }

    // ---- exchange fragments through smem: gsm[row(32)][batch(64)] -----------
    float* gsm = (float*)(smem + SMEM_GSM);
    {
        const int gid = lid >> 2, tig = lid & 3;
#pragma unroll
        for (int g = 0; g < 4; g++) {
            const int col = ncol0 + g * 8 + tig * 2;
            const int r0 = mrow + gid, r1 = r0 + 8;
            gsm[r0 * GSM_STRIDE + col]     = acc[g][0];
            gsm[r0 * GSM_STRIDE + col + 1] = acc[g][1];
            gsm[r1 * GSM_STRIDE + col]     = acc[g][2];
            gsm[r1 * GSM_STRIDE + col + 1] = acc[g][3];
        }
    }
    __syncthreads();

    // ---- fused LSTM cell ----------------------------------------------------
#pragma unroll
    for (int q = 0; q < 4; q++) {
        const int p = tid + q * 128;             // 0..511
        const int b = p >> 3, j = p & 7;
        const int u = bid * 8 + j;
        float iv = gsm[(j)      * GSM_STRIDE + b] + Bp[bid * 32 + j];
        float fv = gsm[(8 + j)  * GSM_STRIDE + b] + Bp[bid * 32 + 8 + j];
        float gv = gsm[(16 + j) * GSM_STRIDE + b] + Bp[bid * 32 + 16 + j];
        float ov = gsm[(24 + j) * GSM_STRIDE + b] + Bp[bid * 32 + 24 + j];
        float cp = Cp[b * HID + u];
        float cn = sigm(fv) * cp + sigm(iv) * tanh_f(gv);
        float hn = sigm(ov) * tanh_f(cn);
        Cp[b * HID + u] = cn;
        if (l == 1) out[((size_t)b * LEN + t) * HID + u] = hn;
        __nv_bfloat16 hi, lo;
        split_bf16(hn, hi, lo);
        char* vd = Vdst + (unsigned)(u >> 6) * VSTG;
        unsigned offd = SWZ((unsigned)(b * 128 + (u & 63) * 2));
        *(__nv_bfloat16*)(vd + offd)        = hi;
        *(__nv_bfloat16*)(vd + 8192 + offd) = lo;
    }
}

extern "C" void kernel_launch(void* const* d_in, const int* in_sizes, int n_in,
                              void* d_out, int out_size) {
    const float* x0  = (const float*)d_in[0];   // [64,1,1024]
    const float* h0  = (const float*)d_in[1];   // [2,64,1024]
    const float* c0  = (const float*)d_in[2];   // [2,64,1024]
    const float* Wih = (const float*)d_in[3];   // [2,4096,1024]
    const float* Whh = (const float*)d_in[4];   // [2,4096,1024]
    const float* bih = (const float*)d_in[5];   // [2,4096]
    const float* bhh = (const float*)d_in[6];   // [2,4096]
    float* out = (float*)d_out;                 // [64,128,1024]

    cudaFuncSetAttribute(lstm_step_mma, cudaFuncAttributeMaxDynamicSharedMemorySize, SMEM_TOTAL);

    convert_weights<<<8192, 256>>>(Wih, Whh);
    init_misc<<<512, 256>>>(x0, h0, c0, bih, bhh);

    for (int t = 0; t < LEN; ++t) {
        lstm_step_mma<<<128, 128, SMEM_TOTAL>>>(0, t, out);
        lstm_step_mma<<<128, 128, SMEM_TOTAL>>>(1, t, out);
    }
}

// round 7
// speedup vs baseline: 6.4008x; 1.0046x over previous
#include <cuda_runtime.h>
#include <cuda_bf16.h>
#include <stdint.h>
#include <math.h>

#define BATCH 64
#define HID   1024
#define LEN   128

#define WSTG   8192            // W stage: 32 rows x 64 k, hi(4KB) + lo(4KB)
#define VSTG   16384           // V stage: 64 rows x 64 k, hi(8KB) + lo(8KB)
#define NSTAGES 32             // K=2048 in 64-chunks (0-15: W_ih seg, 16-31: W_hh seg)
#define NPIPE  4               // smem pipeline depth
#define CTA_WB ((size_t)NSTAGES * WSTG)     // 256KB per (layer, cta)
#define STGB   (WSTG + VSTG)   // 24576 bytes per smem stage

#define SMEM_ST0 1024
#define SMEM_GSM (SMEM_ST0 + NPIPE * STGB)  // 99328
#define GSM_STRIDE 68
#define SMEM_TOTAL (SMEM_GSM + 32 * GSM_STRIDE * 4)   // 108032

#define SWZ(x) ((x) ^ (((x) >> 3) & 0x70))

// ----------------- persistent device state (no runtime allocations) ---------
__device__ __align__(1024) char Wpack[2u * 128u * 262144u];   // 64MB
__device__ __align__(1024) char Vx[16 * VSTG];
__device__ __align__(1024) char V0[2][16 * VSTG];
__device__ __align__(1024) char V1[2][16 * VSTG];
__device__ float Cst[2][BATCH * HID];
__device__ float Bpack[2][4096];

// ----------------- PTX helpers ----------------------------------------------
__device__ __forceinline__ uint32_t smem_u32(const void* p) {
    uint32_t a;
    asm("{ .reg .u64 t; cvta.to.shared.u64 t, %1; cvt.u32.u64 %0, t; }" : "=r"(a) : "l"(p));
    return a;
}
#define MBAR_INIT(a, c) asm volatile("mbarrier.init.shared.b64 [%0], %1;" :: "r"(a), "r"(c) : "memory")
#define MBAR_EXPECT_TX(a, tx) asm volatile("mbarrier.arrive.expect_tx.shared.b64 _, [%0], %1;" :: "r"(a), "r"(tx) : "memory")
#define MBAR_WAIT(addr, ph) do {                                              \
    uint32_t _m = (addr), _p = (ph), _d;                                      \
    asm volatile("{\n\t.reg .pred p;\n\t"                                     \
        "mbarrier.try_wait.parity.acquire.cta.shared::cta.b64 p, [%1], %2;\n\t" \
        "selp.b32 %0, 1, 0, p;\n\t}" : "=r"(_d) : "r"(_m), "r"(_p) : "memory"); \
    if (!_d) {                                                                \
        asm volatile("{\n\t.reg .pred P1;\n\t"                                \
            "WL%=:\n\t"                                                       \
            "mbarrier.try_wait.parity.acquire.cta.shared::cta.b64 P1, [%0], %1, 0x989680;\n\t" \
            "@P1 bra.uni WD%=;\n\t"                                           \
            "bra.uni WL%=;\n\t"                                               \
            "WD%=:\n\t}" :: "r"(_m), "r"(_p) : "memory");                     \
    } } while (0)

#define BULK_G2S(dst, src, bytes, mbar)                                       \
    asm volatile("cp.async.bulk.shared::cta.global.mbarrier::complete_tx::bytes [%0], [%1], %2, [%3];" \
        :: "r"(dst), "l"(src), "r"(bytes), "r"(mbar) : "memory")

__device__ __forceinline__ void ldmx4(uint32_t* r, uint32_t addr) {
    asm volatile("ldmatrix.sync.aligned.m8n8.x4.shared.b16 {%0,%1,%2,%3}, [%4];"
        : "=r"(r[0]), "=r"(r[1]), "=r"(r[2]), "=r"(r[3]) : "r"(addr));
}
__device__ __forceinline__ void mma16816(float* d, const uint32_t* a, const uint32_t* b) {
    asm volatile("mma.sync.aligned.m16n8k16.row.col.f32.bf16.bf16.f32 "
        "{%0,%1,%2,%3}, {%4,%5,%6,%7}, {%8,%9}, {%0,%1,%2,%3};"
        : "+f"(d[0]), "+f"(d[1]), "+f"(d[2]), "+f"(d[3])
        : "r"(a[0]), "r"(a[1]), "r"(a[2]), "r"(a[3]), "r"(b[0]), "r"(b[1]));
}
__device__ __forceinline__ void split_bf16(float v, __nv_bfloat16& hi, __nv_bfloat16& lo) {
    hi = __float2bfloat16(v);
    lo = __float2bfloat16(v - __bfloat162float(hi));
}
__device__ __forceinline__ float sigm(float x) { return 1.0f / (1.0f + __expf(-x)); }
__device__ __forceinline__ float tanh_f(float x) {
    float ax = fabsf(x);
    float t  = __expf(-2.0f * ax);
    return copysignf((1.0f - t) / (1.0f + t), x);
}

// ----------------- one-time (per replay) weight packing ----------------------
__global__ void convert_weights(const float* __restrict__ Wih,
                                const float* __restrict__ Whh) {
    unsigned gid = blockIdx.x * blockDim.x + threadIdx.x;   // < 2097152
    unsigned l    = gid >> 20;
    unsigned rest = gid & 0xFFFFF;
    unsigned seg  = rest >> 19;
    unsigned r2   = rest & 0x7FFFF;
    unsigned r    = r2 >> 7;            // weight row 0..4095
    unsigned k8   = r2 & 127;           // k block of 8

    const float* src = (seg ? Whh : Wih) + (size_t)l * 4096u * 1024u
                     + (size_t)r * 1024u + k8 * 8u;
    float4 v0 = ((const float4*)src)[0];
    float4 v1 = ((const float4*)src)[1];
    float vs[8] = {v0.x, v0.y, v0.z, v0.w, v1.x, v1.y, v1.z, v1.w};

    __nv_bfloat16 hi[8], lo[8];
#pragma unroll
    for (int e = 0; e < 8; e++) split_bf16(vs[e], hi[e], lo[e]);

    unsigned gate = r >> 10, u = r & 1023, bid = u >> 3, j = u & 7;
    unsigned tr = gate * 8 + j;
    unsigned k0 = k8 * 8, stg = seg * 16 + (k0 >> 6), kk = k0 & 63;
    unsigned off = SWZ(tr * 128 + kk * 2);                  // 16B aligned
    char* base = Wpack + ((size_t)(l * 128 + bid)) * CTA_WB + stg * WSTG;

    __nv_bfloat162 p0(hi[0], hi[1]), p1(hi[2], hi[3]), p2(hi[4], hi[5]), p3(hi[6], hi[7]);
    __nv_bfloat162 q0(lo[0], lo[1]), q1(lo[2], lo[3]), q2(lo[4], lo[5]), q3(lo[6], lo[7]);
    *(uint4*)(base + off) =
        make_uint4(*(uint32_t*)&p0, *(uint32_t*)&p1, *(uint32_t*)&p2, *(uint32_t*)&p3);
    *(uint4*)(base + off + 4096) =
        make_uint4(*(uint32_t*)&q0, *(uint32_t*)&q1, *(uint32_t*)&q2, *(uint32_t*)&q3);
}

// ----------------- init: c, biases, initial activation packs -----------------
__global__ void init_misc(const float* __restrict__ x0, const float* __restrict__ h0,
                          const float* __restrict__ c0, const float* __restrict__ bih,
                          const float* __restrict__ bhh) {
    unsigned i = blockIdx.x * blockDim.x + threadIdx.x;     // 131072 threads
    if (i < 131072) ((float*)Cst)[i] = c0[i];
    if (i < 8192) {
        unsigned l = i >> 12, R = i & 4095;
        unsigned bid = R >> 5, rr = R & 31, gate = rr >> 3, j = rr & 7;
        unsigned u = bid * 8 + j;
        unsigned s = l * 4096 + gate * 1024 + u;
        Bpack[l][R] = bih[s] + bhh[s];
    }
    if (i < 3 * 8192) {                                     // activation packing
        unsigned m = i >> 13;                               // 0=Vx, 1=V0, 2=V1
        unsigned p = i & 8191;
        unsigned b = p >> 7, k8 = p & 127, k0 = k8 * 8;
        const float* src = (m == 0) ? (x0 + b * 1024 + k0)
                         : (h0 + (m - 1) * 65536 + b * 1024 + k0);
        char* buf = (m == 0) ? Vx : (m == 1 ? V0[0] : V1[0]);
        float4 v0 = ((const float4*)src)[0];
        float4 v1 = ((const float4*)src)[1];
        float vs[8] = {v0.x, v0.y, v0.z, v0.w, v1.x, v1.y, v1.z, v1.w};
        __nv_bfloat16 hi[8], lo[8];
#pragma unroll
        for (int e = 0; e < 8; e++) split_bf16(vs[e], hi[e], lo[e]);
        unsigned stg = k0 >> 6, kk = k0 & 63;
        unsigned off = SWZ(b * 128 + kk * 2);
        __nv_bfloat162 p0(hi[0], hi[1]), p1(hi[2], hi[3]), p2(hi[4], hi[5]), p3(hi[6], hi[7]);
        __nv_bfloat162 q0(lo[0], lo[1]), q1(lo[2], lo[3]), q2(lo[4], lo[5]), q3(lo[6], lo[7]);
        *(uint4*)(buf + stg * VSTG + off) =
            make_uint4(*(uint32_t*)&p0, *(uint32_t*)&p1, *(uint32_t*)&p2, *(uint32_t*)&p3);
        *(uint4*)(buf + stg * VSTG + 8192 + off) =
            make_uint4(*(uint32_t*)&q0, *(uint32_t*)&q1, *(uint32_t*)&q2, *(uint32_t*)&q3);
    }
}

// ----------------- per (t, layer) fused step ---------------------------------
// CTA bid: units u = bid*8..+7, all gates, all 64 batches. M=32, N=64, K=2048.
// 8 warps, each M16 x N16 (mgrp = wid&1, ngrp = wid>>2... see below).
__global__ void __launch_bounds__(256, 1)
lstm_step_mma(int l, int t, float* __restrict__ out) {
    extern __shared__ __align__(1024) char smem[];
    uint32_t sb = smem_u32(smem);
    const int tid = threadIdx.x, wid = tid >> 5, lid = tid & 31;
    const int bid = blockIdx.x;

    if (tid < NPIPE) MBAR_INIT(sb + tid * 8, 1);
    __syncthreads();

    const char* Wc = Wpack + (size_t)(l * 128 + bid) * CTA_WB;
    const char* Vs0 = (l == 0) ? ((t == 0) ? Vx : V1[t & 1]) : V0[(t + 1) & 1];
    const char* Vs1 = (l == 0) ? V0[t & 1] : V1[t & 1];
    char*       Vdst = (l == 0) ? V0[(t + 1) & 1] : V1[(t + 1) & 1];
    const float* Bp = Bpack[l];
    float*       Cp = Cst[l];

    // warp tile: mgrp in {0,1} -> 16 W-rows; ngrp in {0..3} -> 16 batches
    const int mgrp = wid & 1, ngrp = wid >> 1;
    const int mrow  = mgrp * 16;
    const int ncol0 = ngrp * 16;
    const int blk = lid >> 3, rin = lid & 7;
    const unsigned rbA = (unsigned)((mrow + (blk & 1) * 8 + rin) * 128 + (blk >> 1) * 16);
    const unsigned rbB = (unsigned)((ncol0 + (blk >> 1) * 8 + rin) * 128 + (blk & 1) * 16);

    float aH[2][4], aM[2][4];
#pragma unroll
    for (int g = 0; g < 2; g++)
#pragma unroll
        for (int e = 0; e < 4; e++) { aH[g][e] = 0.0f; aM[g][e] = 0.0f; }

    // prologue: fill pipeline (stages 0..NPIPE-2)
    if (tid == 0) {
#pragma unroll
        for (int s = 0; s < NPIPE - 1; s++) {
            uint32_t fb = sb + s * 8;
            MBAR_EXPECT_TX(fb, STGB);
            uint32_t sdst = sb + SMEM_ST0 + s * STGB;
            const char* vsrc = Vs0 + (size_t)s * VSTG;
            BULK_G2S(sdst, Wc + (size_t)s * WSTG, WSTG, fb);
            BULK_G2S(sdst + WSTG, vsrc, VSTG, fb);
        }
    }

    for (int s = 0; s < NSTAGES; s++) {
        // issue stage s+NPIPE-1 into its slot (consumed slot freed at end of s-1)
        const int ns = s + NPIPE - 1;
        if (ns < NSTAGES && tid == 0) {
            const int slot = ns & (NPIPE - 1);
            uint32_t fb = sb + slot * 8;
            MBAR_EXPECT_TX(fb, STGB);
            uint32_t sdst = sb + SMEM_ST0 + slot * STGB;
            const char* vsrc = ((ns < 16) ? Vs0 : Vs1) + (size_t)(ns & 15) * VSTG;
            BULK_G2S(sdst, Wc + (size_t)ns * WSTG, WSTG, fb);
            BULK_G2S(sdst + WSTG, vsrc, VSTG, fb);
        }
        const int slot = s & (NPIPE - 1);
        MBAR_WAIT(sb + slot * 8, (s >> 2) & 1);

        const uint32_t wb = sb + SMEM_ST0 + slot * STGB;
        const uint32_t vb = wb + WSTG;
#pragma unroll
        for (int kc = 0; kc < 4; kc++) {
            uint32_t ahi[4], alo[4], bhi[4], blo[4];
            const unsigned ko = kc * 32;
            ldmx4(ahi, wb + SWZ(rbA + ko));
            ldmx4(alo, wb + 4096 + SWZ(rbA + ko));
            ldmx4(bhi, vb + SWZ(rbB + ko));
            ldmx4(blo, vb + 8192 + SWZ(rbB + ko));
#pragma unroll
            for (int g = 0; g < 2; g++) {
                mma16816(aH[g], ahi, bhi + g * 2);   // independent chains:
                mma16816(aM[g], ahi, blo + g * 2);   // aH[0], aH[1], aM[0], aM[1]
                mma16816(aM[g], alo, bhi + g * 2);
            }
        }
        __syncthreads();                             // frees this slot for reuse
    }

    // ---- exchange fragments through smem: gsm[row(32)][batch(64)] -----------
    float* gsm = (float*)(smem + SMEM_GSM);
    {
        const int gid = lid >> 2, tig = lid & 3;
#pragma unroll
        for (int g = 0; g < 2; g++) {
            const int col = ncol0 + g * 8 + tig * 2;
            const int r0 = mrow + gid, r1 = r0 + 8;
            gsm[r0 * GSM_STRIDE + col]     = aH[g][0] + aM[g][0];
            gsm[r0 * GSM_STRIDE + col + 1] = aH[g][1] + aM[g][1];
            gsm[r1 * GSM_STRIDE + col]     = aH[g][2] + aM[g][2];
            gsm[r1 * GSM_STRIDE + col + 1] = aH[g][3] + aM[g][3];
        }
    }
    __syncthreads();

    // ---- fused LSTM cell ----------------------------------------------------
#pragma unroll
    for (int q = 0; q < 2; q++) {
        const int p = tid + q * 256;                 // 0..511
        const int b = p >> 3, j = p & 7;
        const int u = bid * 8 + j;
        float iv = gsm[(j)      * GSM_STRIDE + b] + Bp[bid * 32 + j];
        float fv = gsm[(8 + j)  * GSM_STRIDE + b] + Bp[bid * 32 + 8 + j];
        float gv = gsm[(16 + j) * GSM_STRIDE + b] + Bp[bid * 32 + 16 + j];
        float ov = gsm[(24 + j) * GSM_STRIDE + b] + Bp[bid * 32 + 24 + j];
        float cp = Cp[b * HID + u];
        float cn = sigm(fv) * cp + sigm(iv) * tanh_f(gv);
        float hn = sigm(ov) * tanh_f(cn);
        Cp[b * HID + u] = cn;
        if (l == 1) out[((size_t)b * LEN + t) * HID + u] = hn;
        __nv_bfloat16 hi, lo;
        split_bf16(hn, hi, lo);
        char* vd = Vdst + (unsigned)(u >> 6) * VSTG;
        unsigned offd = SWZ((unsigned)(b * 128 + (u & 63) * 2));
        *(__nv_bfloat16*)(vd + offd)        = hi;
        *(__nv_bfloat16*)(vd + 8192 + offd) = lo;
    }
}

extern "C" void kernel_launch(void* const* d_in, const int* in_sizes, int n_in,
                              void* d_out, int out_size) {
    const float* x0  = (const float*)d_in[0];   // [64,1,1024]
    const float* h0  = (const float*)d_in[1];   // [2,64,1024]
    const float* c0  = (const float*)d_in[2];   // [2,64,1024]
    const float* Wih = (const float*)d_in[3];   // [2,4096,1024]
    const float* Whh = (const float*)d_in[4];   // [2,4096,1024]
    const float* bih = (const float*)d_in[5];   // [2,4096]
    const float* bhh = (const float*)d_in[6];   // [2,4096]
    float* out = (float*)d_out;                 // [64,128,1024]

    cudaFuncSetAttribute(lstm_step_mma, cudaFuncAttributeMaxDynamicSharedMemorySize, SMEM_TOTAL);

    convert_weights<<<8192, 256>>>(Wih, Whh);
    init_misc<<<512, 256>>>(x0, h0, c0, bih, bhh);

    for (int t = 0; t < LEN; ++t) {
        lstm_step_mma<<<128, 256, SMEM_TOTAL>>>(0, t, out);
        lstm_step_mma<<<128, 256, SMEM_TOTAL>>>(1, t, out);
    }
}

// round 10
// speedup vs baseline: 9.8654x; 1.5413x over previous
#include <cuda_runtime.h>
#include <cuda_fp16.h>
#include <stdint.h>
#include <math.h>

#define BATCH 64
#define HID   1024
#define LEN   128

#define WSTG   8192            // W stage: 32 rows x 64 k fp16, hi(4KB) + lo(4KB)
#define VSTG   8192            // V stage: 64 rows x 64 k fp16 (single)
#define NSTAGES 32             // K=2048 in 64-chunks (0-15: W_ih seg, 16-31: W_hh seg)
#define NPIPE  8               // smem pipeline depth
#define CTA_WB ((size_t)NSTAGES * WSTG)     // 256KB per (layer, cta)
#define STGB   (WSTG + VSTG)   // 16384 bytes per smem stage
#define LO_SCALE 4096.0f
#define LO_INV   (1.0f / 4096.0f)

#define SMEM_ST0 1024
#define SMEM_GSM (SMEM_ST0 + NPIPE * STGB)  // 132096
#define GSM_STRIDE 68
#define SMEM_TOTAL (SMEM_GSM + 32 * GSM_STRIDE * 4)   // 140800

#define SWZ(x) ((x) ^ (((x) >> 3) & 0x70))

// ----------------- persistent device state (no runtime allocations) ---------
__device__ __align__(1024) char Wpack[2u * 128u * 262144u];   // 64MB
__device__ __align__(1024) char Vx[16 * VSTG];
__device__ __align__(1024) char V0[2][16 * VSTG];
__device__ __align__(1024) char V1[2][16 * VSTG];
__device__ float Cst[2][BATCH * HID];
__device__ float Bpack[2][4096];

// ----------------- PTX helpers ----------------------------------------------
__device__ __forceinline__ uint32_t smem_u32(const void* p) {
    uint32_t a;
    asm("{ .reg .u64 t; cvta.to.shared.u64 t, %1; cvt.u32.u64 %0, t; }" : "=r"(a) : "l"(p));
    return a;
}
#define MBAR_INIT(a, c) asm volatile("mbarrier.init.shared.b64 [%0], %1;" :: "r"(a), "r"(c) : "memory")
#define MBAR_EXPECT_TX(a, tx) asm volatile("mbarrier.arrive.expect_tx.shared.b64 _, [%0], %1;" :: "r"(a), "r"(tx) : "memory")
#define MBAR_ARRIVE(a) asm volatile("mbarrier.arrive.shared.b64 _, [%0];" :: "r"(a) : "memory")
#define MBAR_WAIT(addr, ph) do {                                              \
    uint32_t _m = (addr), _p = (ph), _d;                                      \
    asm volatile("{\n\t.reg .pred p;\n\t"                                     \
        "mbarrier.try_wait.parity.acquire.cta.shared::cta.b64 p, [%1], %2;\n\t" \
        "selp.b32 %0, 1, 0, p;\n\t}" : "=r"(_d) : "r"(_m), "r"(_p) : "memory"); \
    if (!_d) {                                                                \
        asm volatile("{\n\t.reg .pred P1;\n\t"                                \
            "WL%=:\n\t"                                                       \
            "mbarrier.try_wait.parity.acquire.cta.shared::cta.b64 P1, [%0], %1, 0x989680;\n\t" \
            "@P1 bra.uni WD%=;\n\t"                                           \
            "bra.uni WL%=;\n\t"                                               \
            "WD%=:\n\t}" :: "r"(_m), "r"(_p) : "memory");                     \
    } } while (0)

#define BULK_G2S(dst, src, bytes, mbar)                                       \
    asm volatile("cp.async.bulk.shared::cta.global.mbarrier::complete_tx::bytes [%0], [%1], %2, [%3];" \
        :: "r"(dst), "l"(src), "r"(bytes), "r"(mbar) : "memory")

__device__ __forceinline__ void ldmx4(uint32_t* r, uint32_t addr) {
    asm volatile("ldmatrix.sync.aligned.m8n8.x4.shared.b16 {%0,%1,%2,%3}, [%4];"
        : "=r"(r[0]), "=r"(r[1]), "=r"(r[2]), "=r"(r[3]) : "r"(addr));
}
__device__ __forceinline__ void mma16816(float* d, const uint32_t* a, const uint32_t* b) {
    asm volatile("mma.sync.aligned.m16n8k16.row.col.f32.f16.f16.f32 "
        "{%0,%1,%2,%3}, {%4,%5,%6,%7}, {%8,%9}, {%0,%1,%2,%3};"
        : "+f"(d[0]), "+f"(d[1]), "+f"(d[2]), "+f"(d[3])
        : "r"(a[0]), "r"(a[1]), "r"(a[2]), "r"(a[3]), "r"(b[0]), "r"(b[1]));
}
__device__ __forceinline__ float sigm(float x) { return 1.0f / (1.0f + __expf(-x)); }
__device__ __forceinline__ float tanh_f(float x) {
    float ax = fabsf(x);
    float t  = __expf(-2.0f * ax);
    return copysignf((1.0f - t) / (1.0f + t), x);
}

// ----------------- one-time (per replay) weight packing ----------------------
// CTA bid owns units u = bid*8+j; tile row tr = gate*8+j (32 rows). Stage =
// seg*16 + k/64. Per (l,bid): stage*WSTG + SWZ(tr*128 + kk*2); fp16 hi at +0,
// fp16 lo*4096 at +4096. seg0 = W_ih, seg1 = W_hh.
__global__ void convert_weights(const float* __restrict__ Wih,
                                const float* __restrict__ Whh) {
    unsigned gid = blockIdx.x * blockDim.x + threadIdx.x;   // < 2097152
    unsigned l    = gid >> 20;
    unsigned rest = gid & 0xFFFFF;
    unsigned seg  = rest >> 19;
    unsigned r2   = rest & 0x7FFFF;
    unsigned r    = r2 >> 7;            // weight row 0..4095
    unsigned k8   = r2 & 127;           // k block of 8

    const float* src = (seg ? Whh : Wih) + (size_t)l * 4096u * 1024u
                     + (size_t)r * 1024u + k8 * 8u;
    float4 v0 = ((const float4*)src)[0];
    float4 v1 = ((const float4*)src)[1];
    float vs[8] = {v0.x, v0.y, v0.z, v0.w, v1.x, v1.y, v1.z, v1.w};

    __half hi[8], lo[8];
#pragma unroll
    for (int e = 0; e < 8; e++) {
        hi[e] = __float2half(vs[e]);
        lo[e] = __float2half((vs[e] - __half2float(hi[e])) * LO_SCALE);
    }

    unsigned gate = r >> 10, u = r & 1023, bid = u >> 3, j = u & 7;
    unsigned tr = gate * 8 + j;
    unsigned k0 = k8 * 8, stg = seg * 16 + (k0 >> 6), kk = k0 & 63;
    unsigned off = SWZ(tr * 128 + kk * 2);                  // 16B aligned
    char* base = Wpack + ((size_t)(l * 128 + bid)) * CTA_WB + stg * WSTG;

    __half2 p0(hi[0], hi[1]), p1(hi[2], hi[3]), p2(hi[4], hi[5]), p3(hi[6], hi[7]);
    __half2 q0(lo[0], lo[1]), q1(lo[2], lo[3]), q2(lo[4], lo[5]), q3(lo[6], lo[7]);
    *(uint4*)(base + off) =
        make_uint4(*(uint32_t*)&p0, *(uint32_t*)&p1, *(uint32_t*)&p2, *(uint32_t*)&p3);
    *(uint4*)(base + off + 4096) =
        make_uint4(*(uint32_t*)&q0, *(uint32_t*)&q1, *(uint32_t*)&q2, *(uint32_t*)&q3);
}

// ----------------- init: c, biases, initial activation packs -----------------
__global__ void init_misc(const float* __restrict__ x0, const float* __restrict__ h0,
                          const float* __restrict__ c0, const float* __restrict__ bih,
                          const float* __restrict__ bhh) {
    unsigned i = blockIdx.x * blockDim.x + threadIdx.x;     // 131072 threads
    if (i < 131072) ((float*)Cst)[i] = c0[i];
    if (i < 8192) {
        unsigned l = i >> 12, R = i & 4095;
        unsigned bid = R >> 5, rr = R & 31, gate = rr >> 3, j = rr & 7;
        unsigned u = bid * 8 + j;
        unsigned s = l * 4096 + gate * 1024 + u;
        Bpack[l][R] = bih[s] + bhh[s];
    }
    if (i < 3 * 8192) {                                     // activation packing
        unsigned m = i >> 13;                               // 0=Vx, 1=V0, 2=V1
        unsigned p = i & 8191;
        unsigned b = p >> 7, k8 = p & 127, k0 = k8 * 8;
        const float* src = (m == 0) ? (x0 + b * 1024 + k0)
                         : (h0 + (m - 1) * 65536 + b * 1024 + k0);
        char* buf = (m == 0) ? Vx : (m == 1 ? V0[0] : V1[0]);
        float4 v0 = ((const float4*)src)[0];
        float4 v1 = ((const float4*)src)[1];
        float vs[8] = {v0.x, v0.y, v0.z, v0.w, v1.x, v1.y, v1.z, v1.w};
        __half h[8];
#pragma unroll
        for (int e = 0; e < 8; e++) h[e] = __float2half(vs[e]);
        unsigned stg = k0 >> 6, kk = k0 & 63;
        unsigned off = SWZ(b * 128 + kk * 2);
        __half2 p0(h[0], h[1]), p1(h[2], h[3]), p2(h[4], h[5]), p3(h[6], h[7]);
        *(uint4*)(buf + stg * VSTG + off) =
            make_uint4(*(uint32_t*)&p0, *(uint32_t*)&p1, *(uint32_t*)&p2, *(uint32_t*)&p3);
    }
}

// ----------------- per (t, layer) fused step ---------------------------------
// CTA bid: units u = bid*8..+7, all gates, all 64 batches. M=32, N=64, K=2048.
// Warps 0-7 compute (each M16 x N16); warp 8 is the TMA producer.
__global__ void __launch_bounds__(288, 1)
lstm_step_mma(int l, int t, float* __restrict__ out) {
    extern __shared__ __align__(1024) char smem[];
    uint32_t sb = smem_u32(smem);
    const int tid = threadIdx.x, wid = tid >> 5, lid = tid & 31;
    const int bid = blockIdx.x;

    // mbarriers: full[i] at sb + i*8 (count 1 + tx), empty[i] at sb + 64 + i*8 (count 8)
    if (tid < NPIPE) MBAR_INIT(sb + tid * 8, 1);
    else if (tid < 2 * NPIPE) MBAR_INIT(sb + 64 + (tid - NPIPE) * 8, 8);
    __syncthreads();

    const char* Wc = Wpack + (size_t)(l * 128 + bid) * CTA_WB;
    const char* Vs0 = (l == 0) ? ((t == 0) ? Vx : V1[t & 1]) : V0[(t + 1) & 1];
    const char* Vs1 = (l == 0) ? V0[t & 1] : V1[t & 1];
    char*       Vdst = (l == 0) ? V0[(t + 1) & 1] : V1[(t + 1) & 1];
    const float* Bp = Bpack[l];
    float*       Cp = Cst[l];

    if (wid == 8) {
        // ---------------- producer warp ----------------
        if (lid == 0) {
            for (int s = 0; s < NSTAGES; s++) {
                const int slot = s & (NPIPE - 1);
                if (s >= NPIPE) MBAR_WAIT(sb + 64 + slot * 8, ((s >> 3) + 1) & 1);
                uint32_t fb = sb + slot * 8;
                MBAR_EXPECT_TX(fb, STGB);
                uint32_t sdst = sb + SMEM_ST0 + slot * STGB;
                const char* vsrc = ((s < 16) ? Vs0 : Vs1) + (size_t)(s & 15) * VSTG;
                BULK_G2S(sdst, Wc + (size_t)s * WSTG, WSTG, fb);
                BULK_G2S(sdst + WSTG, vsrc, VSTG, fb);
            }
        }
    } else {
        // ---------------- compute warps ----------------
        const int mgrp = wid & 1, ngrp = wid >> 1;
        const int mrow  = mgrp * 16;
        const int ncol0 = ngrp * 16;
        const int blk = lid >> 3, rin = lid & 7;
        const unsigned rbA = (unsigned)((mrow + (blk & 1) * 8 + rin) * 128 + (blk >> 1) * 16);
        const unsigned rbB = (unsigned)((ncol0 + (blk >> 1) * 8 + rin) * 128 + (blk & 1) * 16);

        float aH[2][4], aL[2][4];
#pragma unroll
        for (int g = 0; g < 2; g++)
#pragma unroll
            for (int e = 0; e < 4; e++) { aH[g][e] = 0.0f; aL[g][e] = 0.0f; }

        for (int s = 0; s < NSTAGES; s++) {
            const int slot = s & (NPIPE - 1);
            MBAR_WAIT(sb + slot * 8, (s >> 3) & 1);
            const uint32_t wb = sb + SMEM_ST0 + slot * STGB;
            const uint32_t vb = wb + WSTG;
#pragma unroll
            for (int kc = 0; kc < 4; kc++) {
                uint32_t ahi[4], alo[4], bv[4];
                const unsigned ko = kc * 32;
                ldmx4(ahi, wb + SWZ(rbA + ko));
                ldmx4(alo, wb + 4096 + SWZ(rbA + ko));
                ldmx4(bv, vb + SWZ(rbB + ko));
                mma16816(aH[0], ahi, bv);       // 4 independent chains
                mma16816(aL[0], alo, bv);
                mma16816(aH[1], ahi, bv + 2);
                mma16816(aL[1], alo, bv + 2);
            }
            if (lid == 0) MBAR_ARRIVE(sb + 64 + slot * 8);
        }

        // exchange fragments: gsm[row(32)][batch(64)]
        float* gsm = (float*)(smem + SMEM_GSM);
        const int gid = lid >> 2, tig = lid & 3;
#pragma unroll
        for (int g = 0; g < 2; g++) {
            const int col = ncol0 + g * 8 + tig * 2;
            const int r0 = mrow + gid, r1 = r0 + 8;
            gsm[r0 * GSM_STRIDE + col]     = aH[g][0] + aL[g][0] * LO_INV;
            gsm[r0 * GSM_STRIDE + col + 1] = aH[g][1] + aL[g][1] * LO_INV;
            gsm[r1 * GSM_STRIDE + col]     = aH[g][2] + aL[g][2] * LO_INV;
            gsm[r1 * GSM_STRIDE + col + 1] = aH[g][3] + aL[g][3] * LO_INV;
        }
    }
    __syncthreads();

    // ---- fused LSTM cell (first 256 threads; 512 items) ----------------------
    if (tid < 256) {
        float* gsm = (float*)(smem + SMEM_GSM);
#pragma unroll
        for (int q = 0; q < 2; q++) {
            const int p = tid + q * 256;             // 0..511
            const int b = p >> 3, j = p & 7;
            const int u = bid * 8 + j;
            float iv = gsm[(j)      * GSM_STRIDE + b] + Bp[bid * 32 + j];
            float fv = gsm[(8 + j)  * GSM_STRIDE + b] + Bp[bid * 32 + 8 + j];
            float gv = gsm[(16 + j) * GSM_STRIDE + b] + Bp[bid * 32 + 16 + j];
            float ov = gsm[(24 + j) * GSM_STRIDE + b] + Bp[bid * 32 + 24 + j];
            float cp = Cp[b * HID + u];
            float cn = sigm(fv) * cp + sigm(iv) * tanh_f(gv);
            float hn = sigm(ov) * tanh_f(cn);
            Cp[b * HID + u] = cn;
            if (l == 1) out[((size_t)b * LEN + t) * HID + u] = hn;
            char* vd = Vdst + (unsigned)(u >> 6) * VSTG;
            unsigned offd = SWZ((unsigned)(b * 128 + (u & 63) * 2));
            *(__half*)(vd + offd) = __float2half(hn);
        }
    }
}

extern "C" void kernel_launch(void* const* d_in, const int* in_sizes, int n_in,
                              void* d_out, int out_size) {
    const float* x0  = (const float*)d_in[0];   // [64,1,1024]
    const float* h0  = (const float*)d_in[1];   // [2,64,1024]
    const float* c0  = (const float*)d_in[2];   // [2,64,1024]
    const float* Wih = (const float*)d_in[3];   // [2,4096,1024]
    const float* Whh = (const float*)d_in[4];   // [2,4096,1024]
    const float* bih = (const float*)d_in[5];   // [2,4096]
    const float* bhh = (const float*)d_in[6];   // [2,4096]
    float* out = (float*)d_out;                 // [64,128,1024]

    cudaFuncSetAttribute(lstm_step_mma, cudaFuncAttributeMaxDynamicSharedMemorySize, SMEM_TOTAL);

    convert_weights<<<8192, 256>>>(Wih, Whh);
    init_misc<<<512, 256>>>(x0, h0, c0, bih, bhh);

    for (int t = 0; t < LEN; ++t) {
        lstm_step_mma<<<128, 288, SMEM_TOTAL>>>(0, t, out);
        lstm_step_mma<<<128, 288, SMEM_TOTAL>>>(1, t, out);
    }
}